// round 1
// baseline (speedup 1.0000x reference)
#include <cuda_runtime.h>
#include <cstdint>

// Problem constants (fixed by the dataset)
#define D_IN   4096
#define D_OUT  4096
#define M_TOT  8192     // B*S = 4*2048
#define NEXP   8
#define RANK   4
#define P      32       // NEXP*RANK
#define LSCALE 2.0f     // lora_alpha / rank = 8/4

// Scratch for the down-projection t[m, e*4+r] (raw, no routing weight)
__device__ float g_t[M_TOT * P];

// ---------------------------------------------------------------------------
// Kernel 0: zero the scratch (atomics accumulate into it every launch)
// ---------------------------------------------------------------------------
__global__ void zero_t_kernel() {
    int i = blockIdx.x * 256 + threadIdx.x;
    g_t[i] = 0.0f;
}

// ---------------------------------------------------------------------------
// Kernel 1: t[m, p] += x[m,:] . down_w[p,:]   (down_w viewed as [32, 4096])
// Grid: (M/128, 8 K-splits), 128 threads. Each thread: 8m x 4n accumulators.
// ---------------------------------------------------------------------------
__global__ __launch_bounds__(128)
void down_kernel(const float* __restrict__ x, const float* __restrict__ down_w) {
    __shared__ float As[16][128];
    __shared__ float Bs[16][32];

    const int m0  = blockIdx.x * 128;
    const int k0  = blockIdx.y * 512;
    const int tid = threadIdx.x;
    const int nx  = tid & 7;          // n group: n = nx*4
    const int my  = tid >> 3;         // m group: m = my*8
    const int brow = tid & 31;        // down_w row (p index)
    const int bk4  = (tid >> 5) << 2; // k offset within 16-tile: 0,4,8,12

    float acc[8][4];
#pragma unroll
    for (int i = 0; i < 8; i++)
#pragma unroll
        for (int j = 0; j < 4; j++) acc[i][j] = 0.0f;

    for (int kt = 0; kt < 512; kt += 16) {
        // A tile: 128 rows x 16 k, one row per thread (4 float4 along k), transposed store
        const float4* asrc =
            (const float4*)(x + (size_t)(m0 + tid) * D_IN + k0 + kt);
#pragma unroll
        for (int i = 0; i < 4; i++) {
            float4 v = asrc[i];
            As[i * 4 + 0][tid] = v.x;
            As[i * 4 + 1][tid] = v.y;
            As[i * 4 + 2][tid] = v.z;
            As[i * 4 + 3][tid] = v.w;
        }
        // B tile: 32 rows x 16 k
        float4 bv = *(const float4*)(down_w + (size_t)brow * D_IN + k0 + kt + bk4);
        Bs[bk4 + 0][brow] = bv.x;
        Bs[bk4 + 1][brow] = bv.y;
        Bs[bk4 + 2][brow] = bv.z;
        Bs[bk4 + 3][brow] = bv.w;
        __syncthreads();

#pragma unroll
        for (int kk = 0; kk < 16; kk++) {
            float4 a0 = *(const float4*)&As[kk][my * 8];
            float4 a1 = *(const float4*)&As[kk][my * 8 + 4];
            float4 b  = *(const float4*)&Bs[kk][nx * 4];
            float ra[8] = {a0.x, a0.y, a0.z, a0.w, a1.x, a1.y, a1.z, a1.w};
            float rb[4] = {b.x, b.y, b.z, b.w};
#pragma unroll
            for (int i = 0; i < 8; i++)
#pragma unroll
                for (int j = 0; j < 4; j++) acc[i][j] += ra[i] * rb[j];
        }
        __syncthreads();
    }

#pragma unroll
    for (int i = 0; i < 8; i++)
#pragma unroll
        for (int j = 0; j < 4; j++)
            atomicAdd(&g_t[(size_t)(m0 + my * 8 + i) * P + nx * 4 + j], acc[i][j]);
}

// ---------------------------------------------------------------------------
// Kernel 2: fused main GEMM.
//   out[m,n] = sum_{k<4096} x[m,k]*base_w[n,k]
//            + sum_{p<32} (t[m,p]*LSCALE*route[b(m), p>>2]) * up_w[p>>2, n, p&3]
// Implemented as 516 k-tiles of 8 (512 base + 4 adapter), 128x128 block tile,
// 8x8 per thread, double-buffered smem.
// ---------------------------------------------------------------------------
__global__ __launch_bounds__(256, 2)
void fused_gemm(const float* __restrict__ x, const float* __restrict__ rw,
                const float* __restrict__ base_w, const float* __restrict__ up_w,
                float* __restrict__ out) {
    __shared__ float As[2][8][132];  // [k][m], padded row to dodge bank aliasing
    __shared__ float Bs[2][8][132];  // [k][n]

    const int tid = threadIdx.x;
    const int n0  = blockIdx.x * 128;
    const int m0  = blockIdx.y * 128;
    const int tx  = tid & 15;   // col group
    const int ty  = tid >> 4;   // row group
    const int lrow = tid >> 1;        // 0..127 loader row (m for A, n for B)
    const int lk4  = (tid & 1) * 4;   // 0 or 4 loader k-offset

    float acc[8][8];
#pragma unroll
    for (int i = 0; i < 8; i++)
#pragma unroll
        for (int j = 0; j < 8; j++) acc[i][j] = 0.0f;

    float4 pa, pb;

#define LOAD_TILE(KT)                                                           \
    {                                                                           \
        int kt_ = (KT);                                                         \
        if (kt_ < 512) {                                                        \
            int kk0 = kt_ * 8 + lk4;                                            \
            pa = *(const float4*)(x + (size_t)(m0 + lrow) * D_IN + kk0);        \
            pb = *(const float4*)(base_w + (size_t)(n0 + lrow) * D_IN + kk0);   \
        } else {                                                                \
            int kk0 = (kt_ - 512) * 8 + lk4;       /* 0..28, mult of 4 */       \
            int e   = kk0 >> 2;                                                 \
            float w = LSCALE * rw[((m0 + lrow) >> 11) * NEXP + e];              \
            float4 tv = *(const float4*)(g_t + (size_t)(m0 + lrow) * P + kk0);  \
            pa = make_float4(tv.x * w, tv.y * w, tv.z * w, tv.w * w);           \
            pb = *(const float4*)(up_w + ((size_t)e * D_OUT + (n0 + lrow)) * RANK); \
        }                                                                       \
    }

#define STORE_TILE(BUF)                                                         \
    {                                                                           \
        As[BUF][lk4 + 0][lrow] = pa.x;                                          \
        As[BUF][lk4 + 1][lrow] = pa.y;                                          \
        As[BUF][lk4 + 2][lrow] = pa.z;                                          \
        As[BUF][lk4 + 3][lrow] = pa.w;                                          \
        Bs[BUF][lk4 + 0][lrow] = pb.x;                                          \
        Bs[BUF][lk4 + 1][lrow] = pb.y;                                          \
        Bs[BUF][lk4 + 2][lrow] = pb.z;                                          \
        Bs[BUF][lk4 + 3][lrow] = pb.w;                                          \
    }

    LOAD_TILE(0);
    STORE_TILE(0);
    __syncthreads();

    const int NKT = 516;
    for (int kt = 0; kt < NKT; kt++) {
        const int cur = kt & 1;
        const bool more = (kt + 1 < NKT);
        if (more) LOAD_TILE(kt + 1);

#pragma unroll
        for (int kk = 0; kk < 8; kk++) {
            float4 a0 = *(const float4*)&As[cur][kk][ty * 4];
            float4 a1 = *(const float4*)&As[cur][kk][64 + ty * 4];
            float4 b0 = *(const float4*)&Bs[cur][kk][tx * 4];
            float4 b1 = *(const float4*)&Bs[cur][kk][64 + tx * 4];
            float ra[8] = {a0.x, a0.y, a0.z, a0.w, a1.x, a1.y, a1.z, a1.w};
            float rb[8] = {b0.x, b0.y, b0.z, b0.w, b1.x, b1.y, b1.z, b1.w};
#pragma unroll
            for (int i = 0; i < 8; i++)
#pragma unroll
                for (int j = 0; j < 8; j++) acc[i][j] += ra[i] * rb[j];
        }

        if (more) STORE_TILE(cur ^ 1);
        __syncthreads();
    }

    // Epilogue: each thread owns rows {ty*4+i, 64+ty*4+i} x cols {tx*4.., 64+tx*4..}
#pragma unroll
    for (int i = 0; i < 8; i++) {
        int m = m0 + ((i < 4) ? (ty * 4 + i) : (64 + ty * 4 + (i - 4)));
        float4 c0 = make_float4(acc[i][0], acc[i][1], acc[i][2], acc[i][3]);
        float4 c1 = make_float4(acc[i][4], acc[i][5], acc[i][6], acc[i][7]);
        *(float4*)(out + (size_t)m * D_OUT + n0 + tx * 4)      = c0;
        *(float4*)(out + (size_t)m * D_OUT + n0 + 64 + tx * 4) = c1;
    }
#undef LOAD_TILE
#undef STORE_TILE
}

// ---------------------------------------------------------------------------
// Launch: zero scratch -> down proj -> fused GEMM (same stream, sequential)
// Inputs (metadata order): x, routing_weights, base_w, down_w, up_w
// ---------------------------------------------------------------------------
extern "C" void kernel_launch(void* const* d_in, const int* in_sizes, int n_in,
                              void* d_out, int out_size) {
    const float* x      = (const float*)d_in[0];
    const float* rw     = (const float*)d_in[1];
    const float* base_w = (const float*)d_in[2];
    const float* down_w = (const float*)d_in[3];
    const float* up_w   = (const float*)d_in[4];
    float* out = (float*)d_out;

    zero_t_kernel<<<(M_TOT * P) / 256, 256>>>();
    down_kernel<<<dim3(M_TOT / 128, D_IN / 512), 128>>>(x, down_w);
    fused_gemm<<<dim3(D_OUT / 128, M_TOT / 128), 256>>>(x, rw, base_w, up_w, out);
}

// round 5
// speedup vs baseline: 1.5805x; 1.5805x over previous
#include <cuda_runtime.h>
#include <cuda_bf16.h>
#include <cstdint>

// ---------------------------------------------------------------------------
// Problem constants
// ---------------------------------------------------------------------------
#define D_IN   4096
#define D_OUT  4096
#define M_TOT  8192
#define NEXP   8
#define RANK   4
#define P32    32

// ---------------------------------------------------------------------------
// Device scratch (static; no cudaMalloc allowed)
// ---------------------------------------------------------------------------
__device__ __nv_bfloat16 g_xh[(size_t)M_TOT * D_IN];
__device__ __nv_bfloat16 g_xl[(size_t)M_TOT * D_IN];
__device__ __nv_bfloat16 g_bh[(size_t)D_OUT * D_IN];
__device__ __nv_bfloat16 g_bl[(size_t)D_OUT * D_IN];
__device__ float         g_t [(size_t)M_TOT * P32];
__device__ __nv_bfloat16 g_tA[(size_t)M_TOT * 128];   // [th|tl|th|tl] * 2*rw
__device__ __nv_bfloat16 g_uB[(size_t)D_OUT * 128];   // [uh|uh|ul|ul]

// ---------------------------------------------------------------------------
// Helpers
// ---------------------------------------------------------------------------
__device__ __forceinline__ uint32_t smem_u32(const void* p) {
    uint32_t a;
    asm("{ .reg .u64 t; cvta.to.shared.u64 t, %1; cvt.u32.u64 %0, t; }"
        : "=r"(a) : "l"(p));
    return a;
}
#define CP_ASYNC16(so, g) \
    asm volatile("cp.async.cg.shared.global [%0], [%1], 16;" :: "r"(so), "l"(g))
#define CP_COMMIT() asm volatile("cp.async.commit_group;" ::: "memory")
#define CP_WAIT2()  asm volatile("cp.async.wait_group 2;" ::: "memory")

#define LDSM_X4(r0, r1, r2, r3, addr)                                          \
    asm volatile("ldmatrix.sync.aligned.m8n8.x4.shared.b16 {%0,%1,%2,%3}, [%4];"\
                 : "=r"(r0), "=r"(r1), "=r"(r2), "=r"(r3) : "r"(addr))

#define MMA_16816(c, a, b)                                                     \
    asm volatile("mma.sync.aligned.m16n8k16.row.col.f32.bf16.bf16.f32 "        \
                 "{%0,%1,%2,%3}, {%4,%5,%6,%7}, {%8,%9}, {%0,%1,%2,%3};"       \
                 : "+f"((c)[0]), "+f"((c)[1]), "+f"((c)[2]), "+f"((c)[3])      \
                 : "r"((a)[0]), "r"((a)[1]), "r"((a)[2]), "r"((a)[3]),         \
                   "r"((b)[0]), "r"((b)[1]))

// ---------------------------------------------------------------------------
// Split fp32 -> bf16 hi/lo
// ---------------------------------------------------------------------------
__global__ void split_kernel(const float* __restrict__ src,
                             __nv_bfloat16* __restrict__ dh,
                             __nv_bfloat16* __restrict__ dl) {
    size_t i = ((size_t)blockIdx.x * 256 + threadIdx.x) * 4;
    float4 v = *(const float4*)(src + i);
    __nv_bfloat16 h0 = __float2bfloat16(v.x);
    __nv_bfloat16 h1 = __float2bfloat16(v.y);
    __nv_bfloat16 h2 = __float2bfloat16(v.z);
    __nv_bfloat16 h3 = __float2bfloat16(v.w);
    __nv_bfloat16 l0 = __float2bfloat16(v.x - __bfloat162float(h0));
    __nv_bfloat16 l1 = __float2bfloat16(v.y - __bfloat162float(h1));
    __nv_bfloat16 l2 = __float2bfloat16(v.z - __bfloat162float(h2));
    __nv_bfloat16 l3 = __float2bfloat16(v.w - __bfloat162float(h3));
    *(__nv_bfloat162*)(dh + i)     = __nv_bfloat162(h0, h1);
    *(__nv_bfloat162*)(dh + i + 2) = __nv_bfloat162(h2, h3);
    *(__nv_bfloat162*)(dl + i)     = __nv_bfloat162(l0, l1);
    *(__nv_bfloat162*)(dl + i + 2) = __nv_bfloat162(l2, l3);
}

// ---------------------------------------------------------------------------
// t[m, p] = x[m,:] . down_w[p,:]   (fp32 SIMT)
// ---------------------------------------------------------------------------
__global__ __launch_bounds__(128)
void down_kernel(const float* __restrict__ x, const float* __restrict__ down_w) {
    __shared__ float As[16][128];
    __shared__ float Bs[16][32];
    const int m0  = blockIdx.x * 128;
    const int tid = threadIdx.x;
    const int nx  = tid & 7;
    const int my  = tid >> 3;
    const int brow = tid & 31;
    const int bk4  = (tid >> 5) << 2;

    float acc[8][4];
#pragma unroll
    for (int i = 0; i < 8; i++)
#pragma unroll
        for (int j = 0; j < 4; j++) acc[i][j] = 0.0f;

    for (int kt = 0; kt < D_IN; kt += 16) {
        const float4* asrc = (const float4*)(x + (size_t)(m0 + tid) * D_IN + kt);
#pragma unroll
        for (int i = 0; i < 4; i++) {
            float4 v = asrc[i];
            As[i * 4 + 0][tid] = v.x;
            As[i * 4 + 1][tid] = v.y;
            As[i * 4 + 2][tid] = v.z;
            As[i * 4 + 3][tid] = v.w;
        }
        float4 bv = *(const float4*)(down_w + (size_t)brow * D_IN + kt + bk4);
        Bs[bk4 + 0][brow] = bv.x;
        Bs[bk4 + 1][brow] = bv.y;
        Bs[bk4 + 2][brow] = bv.z;
        Bs[bk4 + 3][brow] = bv.w;
        __syncthreads();
#pragma unroll
        for (int kk = 0; kk < 16; kk++) {
            float4 a0 = *(const float4*)&As[kk][my * 8];
            float4 a1 = *(const float4*)&As[kk][my * 8 + 4];
            float4 b  = *(const float4*)&Bs[kk][nx * 4];
            float ra[8] = {a0.x, a0.y, a0.z, a0.w, a1.x, a1.y, a1.z, a1.w};
            float rb[4] = {b.x, b.y, b.z, b.w};
#pragma unroll
            for (int i = 0; i < 8; i++)
#pragma unroll
                for (int j = 0; j < 4; j++) acc[i][j] += ra[i] * rb[j];
        }
        __syncthreads();
    }
#pragma unroll
    for (int i = 0; i < 8; i++)
#pragma unroll
        for (int j = 0; j < 4; j++)
            g_t[(size_t)(m0 + my * 8 + i) * P32 + nx * 4 + j] = acc[i][j];
}

// ---------------------------------------------------------------------------
// Adapter K-tail operand prep
// g_tA[m] = [th(0:32) | tl(0:32) | th | tl] of t[m,:] * 2*rw[b(m),e]
// g_uB[n] = [uh(0:32) | uh | ul | ul]       of up_w[e,n,r]
// sum over the 128-wide tail = (th+tl)*(uh+ul) = full-precision adapter.
// ---------------------------------------------------------------------------
__global__ void prep_tA(const float* __restrict__ rw) {
    int idx = blockIdx.x * 256 + threadIdx.x;
    int m = idx >> 5, p = idx & 31;
    int b = m >> 11, e = p >> 2;
    float v = g_t[idx] * (2.0f * rw[b * NEXP + e]);
    __nv_bfloat16 th = __float2bfloat16(v);
    __nv_bfloat16 tl = __float2bfloat16(v - __bfloat162float(th));
    __nv_bfloat16* row = g_tA + (size_t)m * 128;
    row[p] = th; row[32 + p] = tl; row[64 + p] = th; row[96 + p] = tl;
}

__global__ void prep_uB(const float* __restrict__ up_w) {
    int idx = blockIdx.x * 256 + threadIdx.x;
    int n = idx >> 5, p = idx & 31;
    int e = p >> 2, r = p & 3;
    float u = up_w[((size_t)e * D_OUT + n) * RANK + r];
    __nv_bfloat16 uh = __float2bfloat16(u);
    __nv_bfloat16 ul = __float2bfloat16(u - __bfloat162float(uh));
    __nv_bfloat16* row = g_uB + (size_t)n * 128;
    row[p] = uh; row[32 + p] = uh; row[64 + p] = ul; row[96 + p] = ul;
}

// ---------------------------------------------------------------------------
// mma.sync GEMM.  CTA tile 128(M) x 256(N), BK=32, 4-stage cp.async pipeline.
// Warp grid 2(m) x 4(n), warp tile 64x64 (m16n8k16 frags: 4 x 8).
// smem rows: 40-element (80 B) stride; data = 64 B (BK=32 bf16) at offsets
// 0/16/32/48; 80*r mod 128 walks all eight 16B banks -> ldmatrix
// conflict-free; rows 16B-aligned for cp.async.
// B is stored n-major with k contiguous -> NON-trans ldmatrix yields the
// required (n = lane>>2, k = 2*(lane&3)) fragment directly.
// K stages: [0,128) xh.bh | [128,256) xh.bl | [256,384) xl.bh | [384,388) tA.uB
// ---------------------------------------------------------------------------
#define BM 128
#define BN 256
#define BK 32
#define RSTRIDE 40                       // elements; 80 bytes
#define A_BYTES (BM * RSTRIDE * 2)       // 10240
#define B_BYTES (BN * RSTRIDE * 2)       // 20480
#define STAGE_BYTES (A_BYTES + B_BYTES)  // 30720
#define NSTAGES 4
#define SMEM_DYN (NSTAGES * STAGE_BYTES) // 122880
#define NST 388

__device__ __forceinline__ void stage_params(int s, const __nv_bfloat16*& ap,
                                             const __nv_bfloat16*& bp,
                                             int& ld, int& k0) {
    if (s < 128)      { ap = g_xh; bp = g_bh; ld = D_IN; k0 = s * BK; }
    else if (s < 256) { ap = g_xh; bp = g_bl; ld = D_IN; k0 = (s - 128) * BK; }
    else if (s < 384) { ap = g_xl; bp = g_bh; ld = D_IN; k0 = (s - 256) * BK; }
    else              { ap = g_tA; bp = g_uB; ld = 128;  k0 = (s - 384) * BK; }
}

// Per stage: A = 128 rows x 4 16B-chunks (512), B = 256 rows x 4 (1024).
// 1536 chunks / 256 threads = 6 cp.async per thread.
__device__ __forceinline__ void load_stage(int s, int buf, int m0, int n0,
                                           int tid, uint32_t smbase) {
    const __nv_bfloat16 *ap, *bp;
    int ld, k0;
    stage_params(s, ap, bp, ld, k0);
    const uint32_t sb = smbase + buf * STAGE_BYTES;
#pragma unroll
    for (int j = 0; j < 2; j++) {            // A: 512 chunks
        int c = j * 256 + tid;
        int row = c >> 2, ch = c & 3;
        const __nv_bfloat16* g = ap + (size_t)(m0 + row) * ld + k0 + ch * 8;
        CP_ASYNC16(sb + row * 80 + ch * 16, g);
    }
#pragma unroll
    for (int j = 0; j < 4; j++) {            // B: 1024 chunks
        int c = j * 256 + tid;
        int row = c >> 2, ch = c & 3;
        const __nv_bfloat16* g = bp + (size_t)(n0 + row) * ld + k0 + ch * 8;
        CP_ASYNC16(sb + A_BYTES + row * 80 + ch * 16, g);
    }
}

__global__ __launch_bounds__(256)
void gemm_mma(float* __restrict__ out) {
    extern __shared__ char smem[];
    const uint32_t smbase = smem_u32(smem);

    const int tid  = threadIdx.x;
    const int wid  = tid >> 5;
    const int lane = tid & 31;
    const int wm   = wid >> 2;          // 0..1
    const int wn   = wid & 3;           // 0..3
    const int n0 = blockIdx.x * BN;
    const int m0 = blockIdx.y * BM;

    float c[4][8][4];
#pragma unroll
    for (int i = 0; i < 4; i++)
#pragma unroll
        for (int j = 0; j < 8; j++)
#pragma unroll
            for (int q = 0; q < 4; q++) c[i][j][q] = 0.0f;

    // ldmatrix per-lane base: lanes 0-15 -> rows 0-15 chunk0, 16-31 -> +16B
    const uint32_t lm_off = (lane & 15) * 80 + (lane >> 4) * 16;
    const uint32_t a_lane = smbase + (wm * 64) * 80 + lm_off;
    const uint32_t b_lane = smbase + A_BYTES + (wn * 64) * 80 + lm_off;

    // Prologue: fill 3 stages
#pragma unroll
    for (int s = 0; s < NSTAGES - 1; s++) {
        load_stage(s, s, m0, n0, tid, smbase);
        CP_COMMIT();
    }

    for (int kt = 0; kt < NST; kt++) {
        const int buf = kt & (NSTAGES - 1);
        CP_WAIT2();
        __syncthreads();

        // prefetch stage kt+3 into the buffer freed by stage kt-1
        if (kt + NSTAGES - 1 < NST)
            load_stage(kt + NSTAGES - 1, (kt + NSTAGES - 1) & (NSTAGES - 1),
                       m0, n0, tid, smbase);
        CP_COMMIT();   // always commit: keeps wait_group ledger uniform

        const uint32_t ab = a_lane + buf * STAGE_BYTES;
        const uint32_t bb = b_lane + buf * STAGE_BYTES;
#pragma unroll
        for (int ks = 0; ks < 2; ks++) {
            uint32_t a[4][4], b[8][2];
#pragma unroll
            for (int mi = 0; mi < 4; mi++)
                LDSM_X4(a[mi][0], a[mi][1], a[mi][2], a[mi][3],
                        ab + mi * 16 * 80 + ks * 32);
#pragma unroll
            for (int nt = 0; nt < 4; nt++)
                LDSM_X4(b[2 * nt][0], b[2 * nt + 1][0],
                        b[2 * nt][1], b[2 * nt + 1][1],
                        bb + nt * 16 * 80 + ks * 32);
#pragma unroll
            for (int mi = 0; mi < 4; mi++)
#pragma unroll
                for (int ni = 0; ni < 8; ni++)
                    MMA_16816(c[mi][ni], a[mi], b[ni]);
        }
        __syncthreads();
    }

    // Epilogue: per-thread frag (row = lane>>2 / +8, col = 2*(lane&3))
    const int rbase = m0 + wm * 64 + (lane >> 2);
    const int cbase = n0 + wn * 64 + 2 * (lane & 3);
#pragma unroll
    for (int mi = 0; mi < 4; mi++) {
#pragma unroll
        for (int ni = 0; ni < 8; ni++) {
            float* p0 = out + (size_t)(rbase + mi * 16) * D_OUT + cbase + ni * 8;
            float* p1 = p0 + 8 * D_OUT;
            *(float2*)p0 = make_float2(c[mi][ni][0], c[mi][ni][1]);
            *(float2*)p1 = make_float2(c[mi][ni][2], c[mi][ni][3]);
        }
    }
}

// ---------------------------------------------------------------------------
// Launch. Inputs (metadata order): x, routing_weights, base_w, down_w, up_w
// ---------------------------------------------------------------------------
extern "C" void kernel_launch(void* const* d_in, const int* in_sizes, int n_in,
                              void* d_out, int out_size) {
    const float* x      = (const float*)d_in[0];
    const float* rw     = (const float*)d_in[1];
    const float* base_w = (const float*)d_in[2];
    const float* down_w = (const float*)d_in[3];
    const float* up_w   = (const float*)d_in[4];
    float* out = (float*)d_out;

    cudaFuncSetAttribute(gemm_mma, cudaFuncAttributeMaxDynamicSharedMemorySize,
                         SMEM_DYN);

    __nv_bfloat16 *xh, *xl, *bh, *bl;
    cudaGetSymbolAddress((void**)&xh, g_xh);
    cudaGetSymbolAddress((void**)&xl, g_xl);
    cudaGetSymbolAddress((void**)&bh, g_bh);
    cudaGetSymbolAddress((void**)&bl, g_bl);

    split_kernel<<<(M_TOT * D_IN) / 1024, 256>>>(x, xh, xl);
    split_kernel<<<(D_OUT * D_IN) / 1024, 256>>>(base_w, bh, bl);
    down_kernel<<<M_TOT / 128, 128>>>(x, down_w);
    prep_tA<<<(M_TOT * P32) / 256, 256>>>(rw);
    prep_uB<<<(D_OUT * P32) / 256, 256>>>(up_w);
    gemm_mma<<<dim3(D_OUT / BN, M_TOT / BM), 256, SMEM_DYN>>>(out);
}

// round 6
// speedup vs baseline: 2.5360x; 1.6046x over previous
#include <cuda_runtime.h>
#include <cuda_fp16.h>
#include <cstdint>

// ---------------------------------------------------------------------------
// Problem constants
// ---------------------------------------------------------------------------
#define D_IN   4096
#define D_OUT  4096
#define M_TOT  8192
#define NEXP   8
#define RANK   4
#define P32    32

// ---------------------------------------------------------------------------
// Device scratch (static; no cudaMalloc allowed)
// ---------------------------------------------------------------------------
__device__ __half g_xh[(size_t)M_TOT * D_IN];   // fp16 hi of x
__device__ __half g_xl[(size_t)M_TOT * D_IN];   // fp16 lo of x (x = xh + xl exactly-ish)
__device__ __half g_bh[(size_t)D_OUT * D_IN];   // fp16 of base_w
__device__ float  g_t [(size_t)M_TOT * P32];    // down proj, fp32
__device__ __half g_tA[(size_t)M_TOT * 64];     // [th(32) | tl(32)] * 2*rw
__device__ __half g_uB[(size_t)D_OUT * 64];     // [uh(32) | uh(32)]

// ---------------------------------------------------------------------------
// Helpers
// ---------------------------------------------------------------------------
__device__ __forceinline__ uint32_t smem_u32(const void* p) {
    uint32_t a;
    asm("{ .reg .u64 t; cvta.to.shared.u64 t, %1; cvt.u32.u64 %0, t; }"
        : "=r"(a) : "l"(p));
    return a;
}
#define CP_ASYNC16(so, g) \
    asm volatile("cp.async.cg.shared.global [%0], [%1], 16;" :: "r"(so), "l"(g))
#define CP_COMMIT() asm volatile("cp.async.commit_group;" ::: "memory")
#define CP_WAIT1()  asm volatile("cp.async.wait_group 1;" ::: "memory")

#define LDSM_X4(r0, r1, r2, r3, addr)                                          \
    asm volatile("ldmatrix.sync.aligned.m8n8.x4.shared.b16 {%0,%1,%2,%3}, [%4];"\
                 : "=r"(r0), "=r"(r1), "=r"(r2), "=r"(r3) : "r"(addr))

#define MMA_16816(c, a, b)                                                     \
    asm volatile("mma.sync.aligned.m16n8k16.row.col.f32.f16.f16.f32 "          \
                 "{%0,%1,%2,%3}, {%4,%5,%6,%7}, {%8,%9}, {%0,%1,%2,%3};"       \
                 : "+f"((c)[0]), "+f"((c)[1]), "+f"((c)[2]), "+f"((c)[3])      \
                 : "r"((a)[0]), "r"((a)[1]), "r"((a)[2]), "r"((a)[3]),         \
                   "r"((b)[0]), "r"((b)[1]))

// ---------------------------------------------------------------------------
// Split fp32 -> fp16 hi/lo  (x = hi + lo, lo captures the fp16 residual)
// ---------------------------------------------------------------------------
__global__ void split_x_kernel(const float* __restrict__ src,
                               __half* __restrict__ dh,
                               __half* __restrict__ dl) {
    size_t i = ((size_t)blockIdx.x * 256 + threadIdx.x) * 4;
    float4 v = *(const float4*)(src + i);
    __half h0 = __float2half(v.x), h1 = __float2half(v.y);
    __half h2 = __float2half(v.z), h3 = __float2half(v.w);
    __half l0 = __float2half(v.x - __half2float(h0));
    __half l1 = __float2half(v.y - __half2float(h1));
    __half l2 = __float2half(v.z - __half2float(h2));
    __half l3 = __float2half(v.w - __half2float(h3));
    *(__half2*)(dh + i)     = __halves2half2(h0, h1);
    *(__half2*)(dh + i + 2) = __halves2half2(h2, h3);
    *(__half2*)(dl + i)     = __halves2half2(l0, l1);
    *(__half2*)(dl + i + 2) = __halves2half2(l2, l3);
}

// fp32 -> fp16 (single rounding; the residual b-lo is the accepted error term)
__global__ void conv_half_kernel(const float* __restrict__ src,
                                 __half* __restrict__ dst) {
    size_t i = ((size_t)blockIdx.x * 256 + threadIdx.x) * 4;
    float4 v = *(const float4*)(src + i);
    *(__half2*)(dst + i)     = __halves2half2(__float2half(v.x), __float2half(v.y));
    *(__half2*)(dst + i + 2) = __halves2half2(__float2half(v.z), __float2half(v.w));
}

// ---------------------------------------------------------------------------
// t[m, p] = x[m,:] . down_w[p,:]   (fp32 SIMT)
// ---------------------------------------------------------------------------
__global__ __launch_bounds__(128)
void down_kernel(const float* __restrict__ x, const float* __restrict__ down_w) {
    __shared__ float As[16][128];
    __shared__ float Bs[16][32];
    const int m0  = blockIdx.x * 128;
    const int tid = threadIdx.x;
    const int nx  = tid & 7;
    const int my  = tid >> 3;
    const int brow = tid & 31;
    const int bk4  = (tid >> 5) << 2;

    float acc[8][4];
#pragma unroll
    for (int i = 0; i < 8; i++)
#pragma unroll
        for (int j = 0; j < 4; j++) acc[i][j] = 0.0f;

    for (int kt = 0; kt < D_IN; kt += 16) {
        const float4* asrc = (const float4*)(x + (size_t)(m0 + tid) * D_IN + kt);
#pragma unroll
        for (int i = 0; i < 4; i++) {
            float4 v = asrc[i];
            As[i * 4 + 0][tid] = v.x;
            As[i * 4 + 1][tid] = v.y;
            As[i * 4 + 2][tid] = v.z;
            As[i * 4 + 3][tid] = v.w;
        }
        float4 bv = *(const float4*)(down_w + (size_t)brow * D_IN + kt + bk4);
        Bs[bk4 + 0][brow] = bv.x;
        Bs[bk4 + 1][brow] = bv.y;
        Bs[bk4 + 2][brow] = bv.z;
        Bs[bk4 + 3][brow] = bv.w;
        __syncthreads();
#pragma unroll
        for (int kk = 0; kk < 16; kk++) {
            float4 a0 = *(const float4*)&As[kk][my * 8];
            float4 a1 = *(const float4*)&As[kk][my * 8 + 4];
            float4 b  = *(const float4*)&Bs[kk][nx * 4];
            float ra[8] = {a0.x, a0.y, a0.z, a0.w, a1.x, a1.y, a1.z, a1.w};
            float rb[4] = {b.x, b.y, b.z, b.w};
#pragma unroll
            for (int i = 0; i < 8; i++)
#pragma unroll
                for (int j = 0; j < 4; j++) acc[i][j] += ra[i] * rb[j];
        }
        __syncthreads();
    }
#pragma unroll
    for (int i = 0; i < 8; i++)
#pragma unroll
        for (int j = 0; j < 4; j++)
            g_t[(size_t)(m0 + my * 8 + i) * P32 + nx * 4 + j] = acc[i][j];
}

// ---------------------------------------------------------------------------
// Adapter tail operand prep (one BK=64 K-stage)
// g_tA[m] = [th(0:32) | tl(0:32)] of t[m,:] * 2*rw[b(m),e]   (exact fp16 pair)
// g_uB[n] = [uh(0:32) | uh(0:32)] of up_w[e,n,r]
// sum over the 64-wide tail = (th+tl)*uh = t * fp16(u).
// ---------------------------------------------------------------------------
__global__ void prep_tA(const float* __restrict__ rw) {
    int idx = blockIdx.x * 256 + threadIdx.x;
    int m = idx >> 5, p = idx & 31;
    int b = m >> 11, e = p >> 2;
    float v = g_t[idx] * (2.0f * rw[b * NEXP + e]);
    __half th = __float2half(v);
    __half tl = __float2half(v - __half2float(th));
    __half* row = g_tA + (size_t)m * 64;
    row[p] = th; row[32 + p] = tl;
}

__global__ void prep_uB(const float* __restrict__ up_w) {
    int idx = blockIdx.x * 256 + threadIdx.x;
    int n = idx >> 5, p = idx & 31;
    int e = p >> 2, r = p & 3;
    __half uh = __float2half(up_w[((size_t)e * D_OUT + n) * RANK + r]);
    __half* row = g_uB + (size_t)n * 64;
    row[p] = uh; row[32 + p] = uh;
}

// ---------------------------------------------------------------------------
// mma.sync GEMM.  CTA 128(M) x 256(N), BK=64, 3-stage cp.async pipeline,
// ONE __syncthreads per iteration (prefetch at kt writes the buffer last
// read at kt-1; the top-of-kt barrier orders those reads before the writes).
// Warp grid 2x4, warp tile 64x64.  smem rows: 144 B stride (128 B data);
// 144*r mod 128 = 16r walks all eight 16B banks -> ldmatrix conflict-free.
// K stages: [0,64) xh.bh | [64,128) xl.bh | 128: tail tA.uB
// ---------------------------------------------------------------------------
#define BM 128
#define BN 256
#define BK 64
#define RSTRB 144                        // bytes per smem row
#define A_BYTES (BM * RSTRB)             // 18432
#define B_BYTES (BN * RSTRB)             // 36864
#define STAGE_BYTES (A_BYTES + B_BYTES)  // 55296
#define NSTAGES 3
#define SMEM_DYN (NSTAGES * STAGE_BYTES) // 165888
#define NST 129

__device__ __forceinline__ void stage_params(int s, const __half*& ap,
                                             const __half*& bp,
                                             int& ld, int& k0) {
    if (s < 64)       { ap = g_xh; bp = g_bh; ld = D_IN; k0 = s * BK; }
    else if (s < 128) { ap = g_xl; bp = g_bh; ld = D_IN; k0 = (s - 64) * BK; }
    else              { ap = g_tA; bp = g_uB; ld = 64;   k0 = 0; }
}

// Per stage: A = 128 rows x 8 16B-chunks (1024), B = 256 x 8 (2048).
// 3072 chunks / 256 threads = 12 cp.async per thread.
__device__ __forceinline__ void load_stage(int s, int buf, int m0, int n0,
                                           int tid, uint32_t smbase) {
    const __half *ap, *bp;
    int ld, k0;
    stage_params(s, ap, bp, ld, k0);
    const uint32_t sb = smbase + buf * STAGE_BYTES;
#pragma unroll
    for (int j = 0; j < 4; j++) {            // A chunks
        int c = j * 256 + tid;
        int row = c >> 3, ch = c & 7;
        const __half* g = ap + (size_t)(m0 + row) * ld + k0 + ch * 8;
        CP_ASYNC16(sb + row * RSTRB + ch * 16, g);
    }
#pragma unroll
    for (int j = 0; j < 8; j++) {            // B chunks
        int c = j * 256 + tid;
        int row = c >> 3, ch = c & 7;
        const __half* g = bp + (size_t)(n0 + row) * ld + k0 + ch * 8;
        CP_ASYNC16(sb + A_BYTES + row * RSTRB + ch * 16, g);
    }
}

__global__ __launch_bounds__(256, 1)
void gemm_mma(float* __restrict__ out) {
    extern __shared__ char smem[];
    const uint32_t smbase = smem_u32(smem);

    const int tid  = threadIdx.x;
    const int wid  = tid >> 5;
    const int lane = tid & 31;
    const int wm   = wid >> 2;          // 0..1
    const int wn   = wid & 3;           // 0..3
    const int n0 = blockIdx.x * BN;
    const int m0 = blockIdx.y * BM;

    float c[4][8][4];
#pragma unroll
    for (int i = 0; i < 4; i++)
#pragma unroll
        for (int j = 0; j < 8; j++)
#pragma unroll
            for (int q = 0; q < 4; q++) c[i][j][q] = 0.0f;

    // ldmatrix per-lane base: lanes 0-15 -> rows 0-15 bytes 0-15,
    // lanes 16-31 -> rows 0-15 bytes 16-31 (matches m16n8k16 frag groups)
    const uint32_t lm_off = (lane & 15) * RSTRB + (lane >> 4) * 16;
    const uint32_t a_lane = smbase + (wm * 64) * RSTRB + lm_off;
    const uint32_t b_lane = smbase + A_BYTES + (wn * 64) * RSTRB + lm_off;

    // Prologue: fill 2 stages
    load_stage(0, 0, m0, n0, tid, smbase);
    CP_COMMIT();
    load_stage(1, 1, m0, n0, tid, smbase);
    CP_COMMIT();

    int buf = 0, bufp2 = 2;
    for (int kt = 0; kt < NST; kt++) {
        CP_WAIT1();
        __syncthreads();

        // prefetch stage kt+2 into the buffer last read at iteration kt-1
        if (kt + 2 < NST)
            load_stage(kt + 2, bufp2, m0, n0, tid, smbase);
        CP_COMMIT();   // always commit: keeps wait_group ledger uniform

        const uint32_t ab = a_lane + buf * STAGE_BYTES;
        const uint32_t bb = b_lane + buf * STAGE_BYTES;
#pragma unroll
        for (int ks = 0; ks < 4; ks++) {
            uint32_t a[4][4], b[8][2];
#pragma unroll
            for (int mi = 0; mi < 4; mi++)
                LDSM_X4(a[mi][0], a[mi][1], a[mi][2], a[mi][3],
                        ab + mi * 16 * RSTRB + ks * 32);
#pragma unroll
            for (int nt = 0; nt < 4; nt++)
                LDSM_X4(b[2 * nt][0], b[2 * nt + 1][0],
                        b[2 * nt][1], b[2 * nt + 1][1],
                        bb + nt * 16 * RSTRB + ks * 32);
#pragma unroll
            for (int mi = 0; mi < 4; mi++)
#pragma unroll
                for (int ni = 0; ni < 8; ni++)
                    MMA_16816(c[mi][ni], a[mi], b[ni]);
        }
        buf   = (buf   == NSTAGES - 1) ? 0 : buf + 1;
        bufp2 = (bufp2 == NSTAGES - 1) ? 0 : bufp2 + 1;
    }

    // Epilogue: per-thread frag (row = lane>>2 / +8, col = 2*(lane&3))
    const int rbase = m0 + wm * 64 + (lane >> 2);
    const int cbase = n0 + wn * 64 + 2 * (lane & 3);
#pragma unroll
    for (int mi = 0; mi < 4; mi++) {
#pragma unroll
        for (int ni = 0; ni < 8; ni++) {
            float* p0 = out + (size_t)(rbase + mi * 16) * D_OUT + cbase + ni * 8;
            float* p1 = p0 + 8 * D_OUT;
            *(float2*)p0 = make_float2(c[mi][ni][0], c[mi][ni][1]);
            *(float2*)p1 = make_float2(c[mi][ni][2], c[mi][ni][3]);
        }
    }
}

// ---------------------------------------------------------------------------
// Launch. Inputs (metadata order): x, routing_weights, base_w, down_w, up_w
// ---------------------------------------------------------------------------
extern "C" void kernel_launch(void* const* d_in, const int* in_sizes, int n_in,
                              void* d_out, int out_size) {
    const float* x      = (const float*)d_in[0];
    const float* rw     = (const float*)d_in[1];
    const float* base_w = (const float*)d_in[2];
    const float* down_w = (const float*)d_in[3];
    const float* up_w   = (const float*)d_in[4];
    float* out = (float*)d_out;

    cudaFuncSetAttribute(gemm_mma, cudaFuncAttributeMaxDynamicSharedMemorySize,
                         SMEM_DYN);

    __half *xh, *xl, *bh;
    cudaGetSymbolAddress((void**)&xh, g_xh);
    cudaGetSymbolAddress((void**)&xl, g_xl);
    cudaGetSymbolAddress((void**)&bh, g_bh);

    split_x_kernel<<<(M_TOT * D_IN) / 1024, 256>>>(x, xh, xl);
    conv_half_kernel<<<(D_OUT * D_IN) / 1024, 256>>>(base_w, bh);
    down_kernel<<<M_TOT / 128, 128>>>(x, down_w);
    prep_tA<<<(M_TOT * P32) / 256, 256>>>(rw);
    prep_uB<<<(D_OUT * P32) / 256, 256>>>(up_w);
    gemm_mma<<<dim3(D_OUT / BN, M_TOT / BM), 256, SMEM_DYN>>>(out);
}

// round 8
// speedup vs baseline: 4.2806x; 1.6879x over previous
#include <cuda_runtime.h>
#include <cuda_fp16.h>
#include <cstdint>

// ---------------------------------------------------------------------------
// Problem constants
// ---------------------------------------------------------------------------
#define D_IN   4096
#define D_OUT  4096
#define M_TOT  8192
#define NEXP   8
#define RANK   4
#define P32    32

// ---------------------------------------------------------------------------
// Device scratch (static; no cudaMalloc allowed)
// ---------------------------------------------------------------------------
__device__ __half g_xh[(size_t)M_TOT * D_IN];   // fp16 of x
__device__ __half g_bh[(size_t)D_OUT * D_IN];   // fp16 of base_w
__device__ float  g_t [(size_t)M_TOT * P32];    // down proj, fp32
__device__ __half g_tA[(size_t)M_TOT * 64];     // [th(32) | tl(32)] * 2*rw
__device__ __half g_uB[(size_t)D_OUT * 64];     // [uh(32) | uh(32)]

// ---------------------------------------------------------------------------
// Helpers
// ---------------------------------------------------------------------------
__device__ __forceinline__ uint32_t smem_u32(const void* p) {
    uint32_t a;
    asm("{ .reg .u64 t; cvta.to.shared.u64 t, %1; cvt.u32.u64 %0, t; }"
        : "=r"(a) : "l"(p));
    return a;
}
#define CP_ASYNC16(so, g) \
    asm volatile("cp.async.cg.shared.global [%0], [%1], 16;" :: "r"(so), "l"(g))
#define CP_COMMIT() asm volatile("cp.async.commit_group;" ::: "memory")
#define CP_WAIT1()  asm volatile("cp.async.wait_group 1;" ::: "memory")

#define LDSM_X4(r0, r1, r2, r3, addr)                                          \
    asm volatile("ldmatrix.sync.aligned.m8n8.x4.shared.b16 {%0,%1,%2,%3}, [%4];"\
                 : "=r"(r0), "=r"(r1), "=r"(r2), "=r"(r3) : "r"(addr))

#define MMA_16816(c, a, b)                                                     \
    asm volatile("mma.sync.aligned.m16n8k16.row.col.f32.f16.f16.f32 "          \
                 "{%0,%1,%2,%3}, {%4,%5,%6,%7}, {%8,%9}, {%0,%1,%2,%3};"       \
                 : "+f"((c)[0]), "+f"((c)[1]), "+f"((c)[2]), "+f"((c)[3])      \
                 : "r"((a)[0]), "r"((a)[1]), "r"((a)[2]), "r"((a)[3]),         \
                   "r"((b)[0]), "r"((b)[1]))

// ---------------------------------------------------------------------------
// fp32 -> fp16 convert (single rounding)
// ---------------------------------------------------------------------------
__global__ void conv_half_kernel(const float* __restrict__ src,
                                 __half* __restrict__ dst) {
    size_t i = ((size_t)blockIdx.x * 256 + threadIdx.x) * 4;
    float4 v = *(const float4*)(src + i);
    *(__half2*)(dst + i)     = __halves2half2(__float2half(v.x), __float2half(v.y));
    *(__half2*)(dst + i + 2) = __halves2half2(__float2half(v.z), __float2half(v.w));
}

// ---------------------------------------------------------------------------
// t[m, p] = x[m,:] . down_w[p,:]   (fp32 SIMT, full precision)
// ---------------------------------------------------------------------------
__global__ __launch_bounds__(128)
void down_kernel(const float* __restrict__ x, const float* __restrict__ down_w) {
    __shared__ float As[16][128];
    __shared__ float Bs[16][32];
    const int m0  = blockIdx.x * 128;
    const int tid = threadIdx.x;
    const int nx  = tid & 7;
    const int my  = tid >> 3;
    const int brow = tid & 31;
    const int bk4  = (tid >> 5) << 2;

    float acc[8][4];
#pragma unroll
    for (int i = 0; i < 8; i++)
#pragma unroll
        for (int j = 0; j < 4; j++) acc[i][j] = 0.0f;

    for (int kt = 0; kt < D_IN; kt += 16) {
        const float4* asrc = (const float4*)(x + (size_t)(m0 + tid) * D_IN + kt);
#pragma unroll
        for (int i = 0; i < 4; i++) {
            float4 v = asrc[i];
            As[i * 4 + 0][tid] = v.x;
            As[i * 4 + 1][tid] = v.y;
            As[i * 4 + 2][tid] = v.z;
            As[i * 4 + 3][tid] = v.w;
        }
        float4 bv = *(const float4*)(down_w + (size_t)brow * D_IN + kt + bk4);
        Bs[bk4 + 0][brow] = bv.x;
        Bs[bk4 + 1][brow] = bv.y;
        Bs[bk4 + 2][brow] = bv.z;
        Bs[bk4 + 3][brow] = bv.w;
        __syncthreads();
#pragma unroll
        for (int kk = 0; kk < 16; kk++) {
            float4 a0 = *(const float4*)&As[kk][my * 8];
            float4 a1 = *(const float4*)&As[kk][my * 8 + 4];
            float4 b  = *(const float4*)&Bs[kk][nx * 4];
            float ra[8] = {a0.x, a0.y, a0.z, a0.w, a1.x, a1.y, a1.z, a1.w};
            float rb[4] = {b.x, b.y, b.z, b.w};
#pragma unroll
            for (int i = 0; i < 8; i++)
#pragma unroll
                for (int j = 0; j < 4; j++) acc[i][j] += ra[i] * rb[j];
        }
        __syncthreads();
    }
#pragma unroll
    for (int i = 0; i < 8; i++)
#pragma unroll
        for (int j = 0; j < 4; j++)
            g_t[(size_t)(m0 + my * 8 + i) * P32 + nx * 4 + j] = acc[i][j];
}

// ---------------------------------------------------------------------------
// Adapter tail operand prep (one BK=64 K-stage)
// g_tA[m] = [th(0:32) | tl(0:32)] of t[m,:] * 2*rw[b(m),e]   (exact fp16 pair)
// g_uB[n] = [uh(0:32) | uh(0:32)] of up_w[e,n,r]
// sum over the 64-wide tail = (th+tl)*uh = t * fp16(u).
// ---------------------------------------------------------------------------
__global__ void prep_tA(const float* __restrict__ rw) {
    int idx = blockIdx.x * 256 + threadIdx.x;
    int m = idx >> 5, p = idx & 31;
    int b = m >> 11, e = p >> 2;
    float v = g_t[idx] * (2.0f * rw[b * NEXP + e]);
    __half th = __float2half(v);
    __half tl = __float2half(v - __half2float(th));
    __half* row = g_tA + (size_t)m * 64;
    row[p] = th; row[32 + p] = tl;
}

__global__ void prep_uB(const float* __restrict__ up_w) {
    int idx = blockIdx.x * 256 + threadIdx.x;
    int n = idx >> 5, p = idx & 31;
    int e = p >> 2, r = p & 3;
    __half uh = __float2half(up_w[((size_t)e * D_OUT + n) * RANK + r]);
    __half* row = g_uB + (size_t)n * 64;
    row[p] = uh; row[32 + p] = uh;
}

// ---------------------------------------------------------------------------
// mma.sync GEMM.  CTA 128(M) x 256(N), BK=64, 3-stage cp.async pipeline,
// one __syncthreads per iteration.  Warp grid 2x4, warp tile 64x64.
// smem rows: 144 B stride (128 B data); 16r mod 128 walks all 8 banks.
// K stages: [0,64) xh.bh | 64: adapter tail tA.uB
// ---------------------------------------------------------------------------
#define BM 128
#define BN 256
#define BK 64
#define RSTRB 144                        // bytes per smem row
#define A_BYTES (BM * RSTRB)             // 18432
#define B_BYTES (BN * RSTRB)             // 36864
#define STAGE_BYTES (A_BYTES + B_BYTES)  // 55296
#define NSTAGES 3
#define SMEM_DYN (NSTAGES * STAGE_BYTES) // 165888
#define NST 65

__device__ __forceinline__ void stage_params(int s, const __half*& ap,
                                             const __half*& bp,
                                             int& ld, int& k0) {
    if (s < 64) { ap = g_xh; bp = g_bh; ld = D_IN; k0 = s * BK; }
    else        { ap = g_tA; bp = g_uB; ld = 64;   k0 = 0; }
}

// Per stage: A = 128 rows x 8 16B-chunks (1024), B = 256 x 8 (2048).
// 3072 chunks / 256 threads = 12 cp.async per thread.
__device__ __forceinline__ void load_stage(int s, int buf, int m0, int n0,
                                           int tid, uint32_t smbase) {
    const __half *ap, *bp;
    int ld, k0;
    stage_params(s, ap, bp, ld, k0);
    const uint32_t sb = smbase + buf * STAGE_BYTES;
#pragma unroll
    for (int j = 0; j < 4; j++) {            // A chunks
        int c = j * 256 + tid;
        int row = c >> 3, ch = c & 7;
        const __half* g = ap + (size_t)(m0 + row) * ld + k0 + ch * 8;
        CP_ASYNC16(sb + row * RSTRB + ch * 16, g);
    }
#pragma unroll
    for (int j = 0; j < 8; j++) {            // B chunks
        int c = j * 256 + tid;
        int row = c >> 3, ch = c & 7;
        const __half* g = bp + (size_t)(n0 + row) * ld + k0 + ch * 8;
        CP_ASYNC16(sb + A_BYTES + row * RSTRB + ch * 16, g);
    }
}

__global__ __launch_bounds__(256, 1)
void gemm_mma(float* __restrict__ out) {
    extern __shared__ char smem[];
    const uint32_t smbase = smem_u32(smem);

    const int tid  = threadIdx.x;
    const int wid  = tid >> 5;
    const int lane = tid & 31;
    const int wm   = wid >> 2;          // 0..1
    const int wn   = wid & 3;           // 0..3
    const int n0 = blockIdx.x * BN;
    const int m0 = blockIdx.y * BM;

    float c[4][8][4];
#pragma unroll
    for (int i = 0; i < 4; i++)
#pragma unroll
        for (int j = 0; j < 8; j++)
#pragma unroll
            for (int q = 0; q < 4; q++) c[i][j][q] = 0.0f;

    // ldmatrix per-lane base: lanes 0-15 -> rows 0-15 bytes 0-15,
    // lanes 16-31 -> rows 0-15 bytes 16-31
    const uint32_t lm_off = (lane & 15) * RSTRB + (lane >> 4) * 16;
    const uint32_t a_lane = smbase + (wm * 64) * RSTRB + lm_off;
    const uint32_t b_lane = smbase + A_BYTES + (wn * 64) * RSTRB + lm_off;

    // Prologue: fill 2 stages
    load_stage(0, 0, m0, n0, tid, smbase);
    CP_COMMIT();
    load_stage(1, 1, m0, n0, tid, smbase);
    CP_COMMIT();

    int buf = 0, bufp2 = 2;
    for (int kt = 0; kt < NST; kt++) {
        CP_WAIT1();
        __syncthreads();

        // prefetch stage kt+2 into the buffer last read at iteration kt-1
        if (kt + 2 < NST)
            load_stage(kt + 2, bufp2, m0, n0, tid, smbase);
        CP_COMMIT();   // always commit: keeps wait_group ledger uniform

        const uint32_t ab = a_lane + buf * STAGE_BYTES;
        const uint32_t bb = b_lane + buf * STAGE_BYTES;
#pragma unroll
        for (int ks = 0; ks < 4; ks++) {
            uint32_t a[4][4], b[8][2];
#pragma unroll
            for (int mi = 0; mi < 4; mi++)
                LDSM_X4(a[mi][0], a[mi][1], a[mi][2], a[mi][3],
                        ab + mi * 16 * RSTRB + ks * 32);
#pragma unroll
            for (int nt = 0; nt < 4; nt++)
                LDSM_X4(b[2 * nt][0], b[2 * nt + 1][0],
                        b[2 * nt][1], b[2 * nt + 1][1],
                        bb + nt * 16 * RSTRB + ks * 32);
#pragma unroll
            for (int mi = 0; mi < 4; mi++)
#pragma unroll
                for (int ni = 0; ni < 8; ni++)
                    MMA_16816(c[mi][ni], a[mi], b[ni]);
        }
        buf   = (buf   == NSTAGES - 1) ? 0 : buf + 1;
        bufp2 = (bufp2 == NSTAGES - 1) ? 0 : bufp2 + 1;
    }

    // Epilogue: per-thread frag (row = lane>>2 / +8, col = 2*(lane&3))
    const int rbase = m0 + wm * 64 + (lane >> 2);
    const int cbase = n0 + wn * 64 + 2 * (lane & 3);
#pragma unroll
    for (int mi = 0; mi < 4; mi++) {
#pragma unroll
        for (int ni = 0; ni < 8; ni++) {
            float* p0 = out + (size_t)(rbase + mi * 16) * D_OUT + cbase + ni * 8;
            float* p1 = p0 + 8 * D_OUT;
            *(float2*)p0 = make_float2(c[mi][ni][0], c[mi][ni][1]);
            *(float2*)p1 = make_float2(c[mi][ni][2], c[mi][ni][3]);
        }
    }
}

// ---------------------------------------------------------------------------
// Launch. Inputs (metadata order): x, routing_weights, base_w, down_w, up_w
// ---------------------------------------------------------------------------
extern "C" void kernel_launch(void* const* d_in, const int* in_sizes, int n_in,
                              void* d_out, int out_size) {
    const float* x      = (const float*)d_in[0];
    const float* rw     = (const float*)d_in[1];
    const float* base_w = (const float*)d_in[2];
    const float* down_w = (const float*)d_in[3];
    const float* up_w   = (const float*)d_in[4];
    float* out = (float*)d_out;

    cudaFuncSetAttribute(gemm_mma, cudaFuncAttributeMaxDynamicSharedMemorySize,
                         SMEM_DYN);

    __half *xh, *bh;
    cudaGetSymbolAddress((void**)&xh, g_xh);
    cudaGetSymbolAddress((void**)&bh, g_bh);

    conv_half_kernel<<<(M_TOT * D_IN) / 1024, 256>>>(x, xh);
    conv_half_kernel<<<(D_OUT * D_IN) / 1024, 256>>>(base_w, bh);
    down_kernel<<<M_TOT / 128, 128>>>(x, down_w);
    prep_tA<<<(M_TOT * P32) / 256, 256>>>(rw);
    prep_uB<<<(D_OUT * P32) / 256, 256>>>(up_w);
    gemm_mma<<<dim3(D_OUT / BN, M_TOT / BM), 256, SMEM_DYN>>>(out);
}

// round 9
// speedup vs baseline: 4.5683x; 1.0672x over previous
#include <cuda_runtime.h>
#include <cuda_fp16.h>
#include <cstdint>

// ---------------------------------------------------------------------------
// Problem constants
// ---------------------------------------------------------------------------
#define D_IN   4096
#define D_OUT  4096
#define M_TOT  8192
#define NEXP   8
#define RANK   4
#define P32    32

// ---------------------------------------------------------------------------
// Device scratch (static; no cudaMalloc allowed)
// ---------------------------------------------------------------------------
__device__ __half g_xh[(size_t)M_TOT * D_IN];   // fp16 of x
__device__ __half g_bh[(size_t)D_OUT * D_IN];   // fp16 of base_w
__device__ __half g_tA[(size_t)M_TOT * 64];     // [th(32) | tl(32)] * 2*rw
__device__ __half g_uB[(size_t)D_OUT * 64];     // [uh(32) | uh(32)]

// ---------------------------------------------------------------------------
// Helpers
// ---------------------------------------------------------------------------
__device__ __forceinline__ uint32_t smem_u32(const void* p) {
    uint32_t a;
    asm("{ .reg .u64 t; cvta.to.shared.u64 t, %1; cvt.u32.u64 %0, t; }"
        : "=r"(a) : "l"(p));
    return a;
}
#define CP_ASYNC16(so, g) \
    asm volatile("cp.async.cg.shared.global [%0], [%1], 16;" :: "r"(so), "l"(g))
#define CP_COMMIT() asm volatile("cp.async.commit_group;" ::: "memory")
#define CP_WAIT2()  asm volatile("cp.async.wait_group 2;" ::: "memory")

#define LDSM_X4(r0, r1, r2, r3, addr)                                          \
    asm volatile("ldmatrix.sync.aligned.m8n8.x4.shared.b16 {%0,%1,%2,%3}, [%4];"\
                 : "=r"(r0), "=r"(r1), "=r"(r2), "=r"(r3) : "r"(addr))

#define MMA_16816(c, a, b)                                                     \
    asm volatile("mma.sync.aligned.m16n8k16.row.col.f32.f16.f16.f32 "          \
                 "{%0,%1,%2,%3}, {%4,%5,%6,%7}, {%8,%9}, {%0,%1,%2,%3};"       \
                 : "+f"((c)[0]), "+f"((c)[1]), "+f"((c)[2]), "+f"((c)[3])      \
                 : "r"((a)[0]), "r"((a)[1]), "r"((a)[2]), "r"((a)[3]),         \
                   "r"((b)[0]), "r"((b)[1]))

// ---------------------------------------------------------------------------
// fp32 -> fp16 convert (single rounding)
// ---------------------------------------------------------------------------
__global__ void conv_half_kernel(const float* __restrict__ src,
                                 __half* __restrict__ dst) {
    size_t i = ((size_t)blockIdx.x * 256 + threadIdx.x) * 4;
    float4 v = *(const float4*)(src + i);
    *(__half2*)(dst + i)     = __halves2half2(__float2half(v.x), __float2half(v.y));
    *(__half2*)(dst + i + 2) = __halves2half2(__float2half(v.z), __float2half(v.w));
}

// ---------------------------------------------------------------------------
// Fused down-projection + adapter-A prep.
// t[m,p] = x[m,:] . down_w[p,:]  (fp32), then immediately:
//   v  = t * 2*rw[b(m), p>>2]
//   g_tA[m] = [fp16_hi(v)(32) | fp16_lo(v)(32)]   (exact fp16 pair)
// Grid: 256 CTAs x 32 rows, 128 threads; thread owns rows {my, my+16} x 4 p.
// ---------------------------------------------------------------------------
__global__ __launch_bounds__(128)
void down_fused(const float* __restrict__ x, const float* __restrict__ down_w,
                const float* __restrict__ rw) {
    __shared__ float As[16][32];
    __shared__ float Bs[16][32];
    const int m0  = blockIdx.x * 32;
    const int tid = threadIdx.x;
    const int nx  = tid & 7;          // p group: p = nx*4 + j  (e = nx>>... = nx? e=p>>2=nx)
    const int my  = tid >> 3;         // 0..15 -> rows my, my+16
    const int lrow = tid >> 2;        // loader row 0..31
    const int lk4  = (tid & 3) * 4;   // loader k offset 0,4,8,12

    float acc[2][4];
#pragma unroll
    for (int i = 0; i < 2; i++)
#pragma unroll
        for (int j = 0; j < 4; j++) acc[i][j] = 0.0f;

    for (int kt = 0; kt < D_IN; kt += 16) {
        float4 av = *(const float4*)(x + (size_t)(m0 + lrow) * D_IN + kt + lk4);
        float4 bv = *(const float4*)(down_w + (size_t)lrow * D_IN + kt + lk4);
        As[lk4 + 0][lrow] = av.x; As[lk4 + 1][lrow] = av.y;
        As[lk4 + 2][lrow] = av.z; As[lk4 + 3][lrow] = av.w;
        Bs[lk4 + 0][lrow] = bv.x; Bs[lk4 + 1][lrow] = bv.y;
        Bs[lk4 + 2][lrow] = bv.z; Bs[lk4 + 3][lrow] = bv.w;
        __syncthreads();
#pragma unroll
        for (int kk = 0; kk < 16; kk++) {
            float a0 = As[kk][my];
            float a1 = As[kk][my + 16];
            float4 b = *(const float4*)&Bs[kk][nx * 4];
            float rb[4] = {b.x, b.y, b.z, b.w};
#pragma unroll
            for (int j = 0; j < 4; j++) {
                acc[0][j] += a0 * rb[j];
                acc[1][j] += a1 * rb[j];
            }
        }
        __syncthreads();
    }

    // Fused prep_tA epilogue: e = (nx*4+j)>>2 = nx
#pragma unroll
    for (int i = 0; i < 2; i++) {
        int m = m0 + my + i * 16;
        float s = 2.0f * rw[(m >> 11) * NEXP + nx];
        __half* row = g_tA + (size_t)m * 64;
#pragma unroll
        for (int j = 0; j < 4; j++) {
            float v = acc[i][j] * s;
            __half th = __float2half(v);
            __half tl = __float2half(v - __half2float(th));
            row[nx * 4 + j]      = th;
            row[32 + nx * 4 + j] = tl;
        }
    }
}

// ---------------------------------------------------------------------------
// g_uB[n] = [uh(0:32) | uh(0:32)] of up_w[e,n,r]
// ---------------------------------------------------------------------------
__global__ void prep_uB(const float* __restrict__ up_w) {
    int idx = blockIdx.x * 256 + threadIdx.x;
    int n = idx >> 5, p = idx & 31;
    int e = p >> 2, r = p & 3;
    __half uh = __float2half(up_w[((size_t)e * D_OUT + n) * RANK + r]);
    __half* row = g_uB + (size_t)n * 64;
    row[p] = uh; row[32 + p] = uh;
}

// ---------------------------------------------------------------------------
// mma.sync GEMM.  CTA 128(M) x 256(N), BK=64, 4-stage cp.async pipeline,
// one __syncthreads per iteration.  Warp grid 2x4, warp tile 64x64.
// smem rows: 144 B stride (128 B data); 16r mod 128 walks all 8 banks.
// K stages: [0,64) xh.bh | 64: adapter tail tA.uB
// ---------------------------------------------------------------------------
#define BM 128
#define BN 256
#define BK 64
#define RSTRB 144                        // bytes per smem row
#define A_BYTES (BM * RSTRB)             // 18432
#define B_BYTES (BN * RSTRB)             // 36864
#define STAGE_BYTES (A_BYTES + B_BYTES)  // 55296
#define NSTAGES 4
#define SMEM_DYN (NSTAGES * STAGE_BYTES) // 221184
#define NST 65

__device__ __forceinline__ void stage_params(int s, const __half*& ap,
                                             const __half*& bp,
                                             int& ld, int& k0) {
    if (s < 64) { ap = g_xh; bp = g_bh; ld = D_IN; k0 = s * BK; }
    else        { ap = g_tA; bp = g_uB; ld = 64;   k0 = 0; }
}

// Per stage: A = 128 rows x 8 16B-chunks (1024), B = 256 x 8 (2048).
// 3072 chunks / 256 threads = 12 cp.async per thread.
__device__ __forceinline__ void load_stage(int s, int buf, int m0, int n0,
                                           int tid, uint32_t smbase) {
    const __half *ap, *bp;
    int ld, k0;
    stage_params(s, ap, bp, ld, k0);
    const uint32_t sb = smbase + buf * STAGE_BYTES;
#pragma unroll
    for (int j = 0; j < 4; j++) {            // A chunks
        int c = j * 256 + tid;
        int row = c >> 3, ch = c & 7;
        const __half* g = ap + (size_t)(m0 + row) * ld + k0 + ch * 8;
        CP_ASYNC16(sb + row * RSTRB + ch * 16, g);
    }
#pragma unroll
    for (int j = 0; j < 8; j++) {            // B chunks
        int c = j * 256 + tid;
        int row = c >> 3, ch = c & 7;
        const __half* g = bp + (size_t)(n0 + row) * ld + k0 + ch * 8;
        CP_ASYNC16(sb + A_BYTES + row * RSTRB + ch * 16, g);
    }
}

__global__ __launch_bounds__(256, 1)
void gemm_mma(float* __restrict__ out) {
    extern __shared__ char smem[];
    const uint32_t smbase = smem_u32(smem);

    const int tid  = threadIdx.x;
    const int wid  = tid >> 5;
    const int lane = tid & 31;
    const int wm   = wid >> 2;          // 0..1
    const int wn   = wid & 3;           // 0..3
    const int n0 = blockIdx.x * BN;
    const int m0 = blockIdx.y * BM;

    float c[4][8][4];
#pragma unroll
    for (int i = 0; i < 4; i++)
#pragma unroll
        for (int j = 0; j < 8; j++)
#pragma unroll
            for (int q = 0; q < 4; q++) c[i][j][q] = 0.0f;

    // ldmatrix per-lane base: lanes 0-15 -> rows 0-15 bytes 0-15,
    // lanes 16-31 -> rows 0-15 bytes 16-31
    const uint32_t lm_off = (lane & 15) * RSTRB + (lane >> 4) * 16;
    const uint32_t a_lane = smbase + (wm * 64) * RSTRB + lm_off;
    const uint32_t b_lane = smbase + A_BYTES + (wn * 64) * RSTRB + lm_off;

    // Prologue: fill 3 stages
    load_stage(0, 0, m0, n0, tid, smbase); CP_COMMIT();
    load_stage(1, 1, m0, n0, tid, smbase); CP_COMMIT();
    load_stage(2, 2, m0, n0, tid, smbase); CP_COMMIT();

    int buf = 0, bufp3 = 3;
    for (int kt = 0; kt < NST; kt++) {
        CP_WAIT2();
        __syncthreads();

        // prefetch stage kt+3 into the buffer last read at iteration kt-1
        if (kt + 3 < NST)
            load_stage(kt + 3, bufp3, m0, n0, tid, smbase);
        CP_COMMIT();   // always commit: keeps wait_group ledger uniform

        const uint32_t ab = a_lane + buf * STAGE_BYTES;
        const uint32_t bb = b_lane + buf * STAGE_BYTES;
#pragma unroll
        for (int ks = 0; ks < 4; ks++) {
            uint32_t a[4][4], b[8][2];
#pragma unroll
            for (int mi = 0; mi < 4; mi++)
                LDSM_X4(a[mi][0], a[mi][1], a[mi][2], a[mi][3],
                        ab + mi * 16 * RSTRB + ks * 32);
#pragma unroll
            for (int nt = 0; nt < 4; nt++)
                LDSM_X4(b[2 * nt][0], b[2 * nt + 1][0],
                        b[2 * nt][1], b[2 * nt + 1][1],
                        bb + nt * 16 * RSTRB + ks * 32);
#pragma unroll
            for (int mi = 0; mi < 4; mi++)
#pragma unroll
                for (int ni = 0; ni < 8; ni++)
                    MMA_16816(c[mi][ni], a[mi], b[ni]);
        }
        buf   = (buf   == NSTAGES - 1) ? 0 : buf + 1;
        bufp3 = (bufp3 == NSTAGES - 1) ? 0 : bufp3 + 1;
    }

    // Epilogue: per-thread frag (row = lane>>2 / +8, col = 2*(lane&3))
    const int rbase = m0 + wm * 64 + (lane >> 2);
    const int cbase = n0 + wn * 64 + 2 * (lane & 3);
#pragma unroll
    for (int mi = 0; mi < 4; mi++) {
#pragma unroll
        for (int ni = 0; ni < 8; ni++) {
            float* p0 = out + (size_t)(rbase + mi * 16) * D_OUT + cbase + ni * 8;
            float* p1 = p0 + 8 * D_OUT;
            *(float2*)p0 = make_float2(c[mi][ni][0], c[mi][ni][1]);
            *(float2*)p1 = make_float2(c[mi][ni][2], c[mi][ni][3]);
        }
    }
}

// ---------------------------------------------------------------------------
// Launch. Inputs (metadata order): x, routing_weights, base_w, down_w, up_w
// ---------------------------------------------------------------------------
extern "C" void kernel_launch(void* const* d_in, const int* in_sizes, int n_in,
                              void* d_out, int out_size) {
    const float* x      = (const float*)d_in[0];
    const float* rw     = (const float*)d_in[1];
    const float* base_w = (const float*)d_in[2];
    const float* down_w = (const float*)d_in[3];
    const float* up_w   = (const float*)d_in[4];
    float* out = (float*)d_out;

    cudaFuncSetAttribute(gemm_mma, cudaFuncAttributeMaxDynamicSharedMemorySize,
                         SMEM_DYN);

    __half *xh, *bh;
    cudaGetSymbolAddress((void**)&xh, g_xh);
    cudaGetSymbolAddress((void**)&bh, g_bh);

    conv_half_kernel<<<(M_TOT * D_IN) / 1024, 256>>>(x, xh);
    conv_half_kernel<<<(D_OUT * D_IN) / 1024, 256>>>(base_w, bh);
    down_fused<<<M_TOT / 32, 128>>>(x, down_w, rw);
    prep_uB<<<(D_OUT * P32) / 256, 256>>>(up_w);
    gemm_mma<<<dim3(D_OUT / BN, M_TOT / BM), 256, SMEM_DYN>>>(out);
}

// round 10
// speedup vs baseline: 4.5693x; 1.0002x over previous
#include <cuda_runtime.h>
#include <cuda_fp16.h>
#include <cstdint>

// ---------------------------------------------------------------------------
// Problem constants
// ---------------------------------------------------------------------------
#define D_IN   4096
#define D_OUT  4096
#define M_TOT  8192
#define NEXP   8
#define RANK   4
#define P32    32

// ---------------------------------------------------------------------------
// Device scratch (static; no cudaMalloc allowed)
// ---------------------------------------------------------------------------
__device__ __half g_xh[(size_t)M_TOT * D_IN];   // fp16 of x (written by down_fused)
__device__ __half g_bh[(size_t)D_OUT * D_IN];   // fp16 of base_w
__device__ __half g_tA[(size_t)M_TOT * 64];     // [th(32) | tl(32)] * 2*rw
__device__ __half g_uB[(size_t)D_OUT * 64];     // [uh(32) | uh(32)]

// ---------------------------------------------------------------------------
// Helpers
// ---------------------------------------------------------------------------
__device__ __forceinline__ uint32_t smem_u32(const void* p) {
    uint32_t a;
    asm("{ .reg .u64 t; cvta.to.shared.u64 t, %1; cvt.u32.u64 %0, t; }"
        : "=r"(a) : "l"(p));
    return a;
}
#define CP_ASYNC16(so, g) \
    asm volatile("cp.async.cg.shared.global [%0], [%1], 16;" :: "r"(so), "l"(g))
#define CP_COMMIT() asm volatile("cp.async.commit_group;" ::: "memory")
#define CP_WAIT2()  asm volatile("cp.async.wait_group 2;" ::: "memory")

#define LDSM_X4(r0, r1, r2, r3, addr)                                          \
    asm volatile("ldmatrix.sync.aligned.m8n8.x4.shared.b16 {%0,%1,%2,%3}, [%4];"\
                 : "=r"(r0), "=r"(r1), "=r"(r2), "=r"(r3) : "r"(addr))

#define MMA_16816(c, a, b)                                                     \
    asm volatile("mma.sync.aligned.m16n8k16.row.col.f32.f16.f16.f32 "          \
                 "{%0,%1,%2,%3}, {%4,%5,%6,%7}, {%8,%9}, {%0,%1,%2,%3};"       \
                 : "+f"((c)[0]), "+f"((c)[1]), "+f"((c)[2]), "+f"((c)[3])      \
                 : "r"((a)[0]), "r"((a)[1]), "r"((a)[2]), "r"((a)[3]),         \
                   "r"((b)[0]), "r"((b)[1]))

// ---------------------------------------------------------------------------
// fp32 -> fp16 convert (used for base_w only; x conversion fused below)
// ---------------------------------------------------------------------------
__global__ void conv_half_kernel(const float* __restrict__ src,
                                 __half* __restrict__ dst) {
    size_t i = ((size_t)blockIdx.x * 256 + threadIdx.x) * 4;
    float4 v = *(const float4*)(src + i);
    *(__half2*)(dst + i)     = __halves2half2(__float2half(v.x), __float2half(v.y));
    *(__half2*)(dst + i + 2) = __halves2half2(__float2half(v.z), __float2half(v.w));
}

// ---------------------------------------------------------------------------
// Fused: down-projection + adapter-A prep + x -> fp16 conversion.
// t[m,p] = x[m,:] . down_w[p,:]  (fp32), then
//   v = t * 2*rw[b(m), p>>2];  g_tA[m] = [fp16_hi(v) | fp16_lo(v)]
// Loader also emits g_xh = fp16(x) (each element covered exactly once).
// Grid: 256 CTAs x 32 rows, 128 threads; thread owns rows {my, my+16} x 4 p.
// ---------------------------------------------------------------------------
__global__ __launch_bounds__(128)
void down_fused(const float* __restrict__ x, const float* __restrict__ down_w,
                const float* __restrict__ rw) {
    __shared__ float As[16][32];
    __shared__ float Bs[16][32];
    const int m0  = blockIdx.x * 32;
    const int tid = threadIdx.x;
    const int nx  = tid & 7;          // p group: p = nx*4 + j, e = nx
    const int my  = tid >> 3;         // 0..15 -> rows my, my+16
    const int lrow = tid >> 2;        // loader row 0..31
    const int lk4  = (tid & 3) * 4;   // loader k offset 0,4,8,12

    float acc[2][4];
#pragma unroll
    for (int i = 0; i < 2; i++)
#pragma unroll
        for (int j = 0; j < 4; j++) acc[i][j] = 0.0f;

    for (int kt = 0; kt < D_IN; kt += 16) {
        float4 av = *(const float4*)(x + (size_t)(m0 + lrow) * D_IN + kt + lk4);
        float4 bv = *(const float4*)(down_w + (size_t)lrow * D_IN + kt + lk4);
        // fused x -> fp16 (each (row,k) covered exactly once across the grid)
        __half2 h01 = __floats2half2_rn(av.x, av.y);
        __half2 h23 = __floats2half2_rn(av.z, av.w);
        __half* xd = g_xh + (size_t)(m0 + lrow) * D_IN + kt + lk4;
        *(__half2*)(xd)     = h01;
        *(__half2*)(xd + 2) = h23;

        As[lk4 + 0][lrow] = av.x; As[lk4 + 1][lrow] = av.y;
        As[lk4 + 2][lrow] = av.z; As[lk4 + 3][lrow] = av.w;
        Bs[lk4 + 0][lrow] = bv.x; Bs[lk4 + 1][lrow] = bv.y;
        Bs[lk4 + 2][lrow] = bv.z; Bs[lk4 + 3][lrow] = bv.w;
        __syncthreads();
#pragma unroll
        for (int kk = 0; kk < 16; kk++) {
            float a0 = As[kk][my];
            float a1 = As[kk][my + 16];
            float4 b = *(const float4*)&Bs[kk][nx * 4];
            float rb[4] = {b.x, b.y, b.z, b.w};
#pragma unroll
            for (int j = 0; j < 4; j++) {
                acc[0][j] += a0 * rb[j];
                acc[1][j] += a1 * rb[j];
            }
        }
        __syncthreads();
    }

#pragma unroll
    for (int i = 0; i < 2; i++) {
        int m = m0 + my + i * 16;
        float s = 2.0f * rw[(m >> 11) * NEXP + nx];
        __half* row = g_tA + (size_t)m * 64;
#pragma unroll
        for (int j = 0; j < 4; j++) {
            float v = acc[i][j] * s;
            __half th = __float2half(v);
            __half tl = __float2half(v - __half2float(th));
            row[nx * 4 + j]      = th;
            row[32 + nx * 4 + j] = tl;
        }
    }
}

// ---------------------------------------------------------------------------
// g_uB[n] = [uh(0:32) | uh(0:32)] of up_w[e,n,r]
// ---------------------------------------------------------------------------
__global__ void prep_uB(const float* __restrict__ up_w) {
    int idx = blockIdx.x * 256 + threadIdx.x;
    int n = idx >> 5, p = idx & 31;
    int e = p >> 2, r = p & 3;
    __half uh = __float2half(up_w[((size_t)e * D_OUT + n) * RANK + r]);
    __half* row = g_uB + (size_t)n * 64;
    row[p] = uh; row[32 + p] = uh;
}

// ---------------------------------------------------------------------------
// Persistent mma.sync GEMM.  148 CTAs; each loops over tiles t = bid + i*148
// of the 16(N) x 64(M) tile grid with a CONTINUOUS cp.async pipeline across
// tile boundaries (global stage index = tile*65 + s).
// Tile 128(M) x 256(N), BK=64, 4-stage pipeline, warp grid 2x4 (64x64/warp).
// smem rows: 144 B stride; K stages per tile: [0,64) xh.bh | 64: tail tA.uB
// ---------------------------------------------------------------------------
#define BM 128
#define BN 256
#define BK 64
#define RSTRB 144
#define A_BYTES (BM * RSTRB)             // 18432
#define B_BYTES (BN * RSTRB)             // 36864
#define STAGE_BYTES (A_BYTES + B_BYTES)  // 55296
#define NSTAGES 4
#define SMEM_DYN (NSTAGES * STAGE_BYTES) // 221184
#define NST 65
#define NTILES 1024                      // (4096/256) * (8192/128)
#define GRID_CTAS 148

__device__ __forceinline__ void tile_mn(int bid, int tl, int& m0, int& n0) {
    int t = bid + tl * GRID_CTAS;
    n0 = (t & 15) * BN;
    m0 = (t >> 4) * BM;
}

__device__ __forceinline__ void stage_params(int s, const __half*& ap,
                                             const __half*& bp,
                                             int& ld, int& k0) {
    if (s < 64) { ap = g_xh; bp = g_bh; ld = D_IN; k0 = s * BK; }
    else        { ap = g_tA; bp = g_uB; ld = 64;   k0 = 0; }
}

__device__ __forceinline__ void load_stage(int s, int buf, int m0, int n0,
                                           int tid, uint32_t smbase) {
    const __half *ap, *bp;
    int ld, k0;
    stage_params(s, ap, bp, ld, k0);
    const uint32_t sb = smbase + buf * STAGE_BYTES;
#pragma unroll
    for (int j = 0; j < 4; j++) {            // A: 1024 chunks
        int c = j * 256 + tid;
        int row = c >> 3, ch = c & 7;
        const __half* g = ap + (size_t)(m0 + row) * ld + k0 + ch * 8;
        CP_ASYNC16(sb + row * RSTRB + ch * 16, g);
    }
#pragma unroll
    for (int j = 0; j < 8; j++) {            // B: 2048 chunks
        int c = j * 256 + tid;
        int row = c >> 3, ch = c & 7;
        const __half* g = bp + (size_t)(n0 + row) * ld + k0 + ch * 8;
        CP_ASYNC16(sb + A_BYTES + row * RSTRB + ch * 16, g);
    }
}

__global__ __launch_bounds__(256, 1)
void gemm_mma(float* __restrict__ out) {
    extern __shared__ char smem[];
    const uint32_t smbase = smem_u32(smem);

    const int tid  = threadIdx.x;
    const int wid  = tid >> 5;
    const int lane = tid & 31;
    const int wm   = wid >> 2;          // 0..1
    const int wn   = wid & 3;           // 0..3
    const int bid  = blockIdx.x;

    const int nt_local = (NTILES - bid + GRID_CTAS - 1) / GRID_CTAS;
    const int total = nt_local * NST;

    float c[4][8][4];
#pragma unroll
    for (int i = 0; i < 4; i++)
#pragma unroll
        for (int j = 0; j < 8; j++)
#pragma unroll
            for (int q = 0; q < 4; q++) c[i][j][q] = 0.0f;

    const uint32_t lm_off = (lane & 15) * RSTRB + (lane >> 4) * 16;
    const uint32_t a_lane = smbase + (wm * 64) * RSTRB + lm_off;
    const uint32_t b_lane = smbase + A_BYTES + (wn * 64) * RSTRB + lm_off;

    // Prefetch cursor (next global stage to load)
    int pf_s = 0, pf_tl = 0, pf_m0, pf_n0;
    tile_mn(bid, 0, pf_m0, pf_n0);
    // Current-compute cursor
    int cur_s = 0, cur_tl = 0, cur_m0, cur_n0;
    tile_mn(bid, 0, cur_m0, cur_n0);

    // Prologue: fill 3 stages
#pragma unroll
    for (int i = 0; i < NSTAGES - 1; i++) {
        load_stage(pf_s, i, pf_m0, pf_n0, tid, smbase);
        CP_COMMIT();
        if (++pf_s == NST) {
            pf_s = 0;
            if (++pf_tl < nt_local) tile_mn(bid, pf_tl, pf_m0, pf_n0);
        }
    }

    int buf = 0, bufp = NSTAGES - 1;
    for (int it = 0; it < total; it++) {
        CP_WAIT2();
        __syncthreads();

        if (it + NSTAGES - 1 < total) {
            load_stage(pf_s, bufp, pf_m0, pf_n0, tid, smbase);
            if (++pf_s == NST) {
                pf_s = 0;
                if (++pf_tl < nt_local) tile_mn(bid, pf_tl, pf_m0, pf_n0);
            }
        }
        CP_COMMIT();   // always commit: keeps wait_group ledger uniform

        const uint32_t ab = a_lane + buf * STAGE_BYTES;
        const uint32_t bb = b_lane + buf * STAGE_BYTES;
#pragma unroll
        for (int ks = 0; ks < 4; ks++) {
            uint32_t a[4][4], b[8][2];
#pragma unroll
            for (int mi = 0; mi < 4; mi++)
                LDSM_X4(a[mi][0], a[mi][1], a[mi][2], a[mi][3],
                        ab + mi * 16 * RSTRB + ks * 32);
#pragma unroll
            for (int nt = 0; nt < 4; nt++)
                LDSM_X4(b[2 * nt][0], b[2 * nt + 1][0],
                        b[2 * nt][1], b[2 * nt + 1][1],
                        bb + nt * 16 * RSTRB + ks * 32);
#pragma unroll
            for (int mi = 0; mi < 4; mi++)
#pragma unroll
                for (int ni = 0; ni < 8; ni++)
                    MMA_16816(c[mi][ni], a[mi], b[ni]);
        }

        if (cur_s == NST - 1) {
            // Tile finished: epilogue (overlaps with in-flight prefetches)
            const int rbase = cur_m0 + wm * 64 + (lane >> 2);
            const int cbase = cur_n0 + wn * 64 + 2 * (lane & 3);
#pragma unroll
            for (int mi = 0; mi < 4; mi++) {
#pragma unroll
                for (int ni = 0; ni < 8; ni++) {
                    float* p0 = out + (size_t)(rbase + mi * 16) * D_OUT + cbase + ni * 8;
                    float* p1 = p0 + 8 * D_OUT;
                    *(float2*)p0 = make_float2(c[mi][ni][0], c[mi][ni][1]);
                    *(float2*)p1 = make_float2(c[mi][ni][2], c[mi][ni][3]);
                }
            }
#pragma unroll
            for (int i = 0; i < 4; i++)
#pragma unroll
                for (int j = 0; j < 8; j++)
#pragma unroll
                    for (int q = 0; q < 4; q++) c[i][j][q] = 0.0f;
            cur_s = 0;
            if (++cur_tl < nt_local) tile_mn(bid, cur_tl, cur_m0, cur_n0);
        } else {
            cur_s++;
        }

        buf  = (buf  == NSTAGES - 1) ? 0 : buf + 1;
        bufp = (bufp == NSTAGES - 1) ? 0 : bufp + 1;
    }
}

// ---------------------------------------------------------------------------
// Launch. Inputs (metadata order): x, routing_weights, base_w, down_w, up_w
// ---------------------------------------------------------------------------
extern "C" void kernel_launch(void* const* d_in, const int* in_sizes, int n_in,
                              void* d_out, int out_size) {
    const float* x      = (const float*)d_in[0];
    const float* rw     = (const float*)d_in[1];
    const float* base_w = (const float*)d_in[2];
    const float* down_w = (const float*)d_in[3];
    const float* up_w   = (const float*)d_in[4];
    float* out = (float*)d_out;

    cudaFuncSetAttribute(gemm_mma, cudaFuncAttributeMaxDynamicSharedMemorySize,
                         SMEM_DYN);

    __half* bh;
    cudaGetSymbolAddress((void**)&bh, g_bh);

    down_fused<<<M_TOT / 32, 128>>>(x, down_w, rw);          // t, tA, xh
    conv_half_kernel<<<(D_OUT * D_IN) / 1024, 256>>>(base_w, bh);
    prep_uB<<<(D_OUT * P32) / 256, 256>>>(up_w);
    gemm_mma<<<GRID_CTAS, 256, SMEM_DYN>>>(out);
}